// round 16
// baseline (speedup 1.0000x reference)
#include <cuda_runtime.h>
#include <cuda_fp16.h>
#include <cstdint>

// Problem dims (fixed per reference)
#define BQ 8
#define LQ 4096
#define HQ 768
#define PQ 256
#define ROWS (BQ*LQ)        // 32768
#define LC 32               // timesteps per thread in fused scan
#define NCHUNK (LQ/LC)      // 128 = threads per scan block

// GEMM tiling (fp16 operands) — R12/R15-verified: CTA 128x128, warps 2x4 of 64x32
#define BM 128
#define BN 128
#define KC 64               // halfs per stage-row = 128 bytes
#define NSTG 3
#define ASZ (BM*KC*2)       // 16 KB
#define BSZ (BN*KC*2)       // 16 KB
#define STG (ASZ+BSZ)       // 32 KB
#define GSMEM (NSTG*STG)    // 96 KB

// ---------------- scratch (__device__ globals) ------------------------------
__device__ __half g_Wh[3*PQ * HQ];               // [n=768][k=768] K-major fp16
__device__ __half g_Ch[HQ * 2*PQ];               // [n=768][k=512] K-major fp16
__device__ __half g_uh[(size_t)ROWS * HQ];       // fp16 copy of u
__device__ __half g_Yh[(size_t)ROWS * 3 * PQ];   // dt-logit | Bu_re | Bu_im (fp16)
__device__ __half g_Xh[(size_t)ROWS * 2 * PQ];   // x_re | x_im (fp16)

// ---------------- helpers ---------------------------------------------------
__device__ __forceinline__ uint32_t smem_u32(const void* p) {
    uint32_t a;
    asm("{ .reg .u64 t; cvta.to.shared.u64 t, %1; cvt.u32.u64 %0, t; }" : "=r"(a) : "l"(p));
    return a;
}
__device__ __forceinline__ void cp16(uint32_t smem, const void* gmem) {
    asm volatile("cp.async.cg.shared.global [%0], [%1], 16;" :: "r"(smem), "l"(gmem) : "memory");
}
#define CP_COMMIT()  asm volatile("cp.async.commit_group;" ::: "memory")
#define CP_WAIT(n)   asm volatile("cp.async.wait_group %0;" :: "n"(n) : "memory")

#define LDSM_X4(r0,r1,r2,r3,addr) \
    asm volatile("ldmatrix.sync.aligned.m8n8.x4.shared.b16 {%0,%1,%2,%3}, [%4];" \
        : "=r"(r0),"=r"(r1),"=r"(r2),"=r"(r3) : "r"(addr))

#define MMA_F16(c, a, b) \
    asm volatile("mma.sync.aligned.m16n8k16.row.col.f32.f16.f16.f32 " \
        "{%0,%1,%2,%3}, {%4,%5,%6,%7}, {%8,%9}, {%0,%1,%2,%3};" \
        : "+f"((c)[0]),"+f"((c)[1]),"+f"((c)[2]),"+f"((c)[3]) \
        : "r"((a)[0]),"r"((a)[1]),"r"((a)[2]),"r"((a)[3]), "r"((b)[0]),"r"((b)[1]))

// ---------------- prep kernels ----------------------------------------------
__global__ void convert_u(const float4* __restrict__ in, __half2* __restrict__ out, int n4) {
    int i = blockIdx.x * blockDim.x + threadIdx.x;
    if (i >= n4) return;
    float4 v = in[i];
    out[2*i]   = __floats2half2_rn(v.x, v.y);
    out[2*i+1] = __floats2half2_rn(v.z, v.w);
}

// merged weight prep: first 3*PQ*HQ elements -> g_Wh, rest -> g_Ch
__global__ void prep_weights(const float* __restrict__ W_dt,
                             const float* __restrict__ B_re,
                             const float* __restrict__ B_im,
                             const float* __restrict__ C_re,
                             const float* __restrict__ C_im) {
    int idx = blockIdx.x * blockDim.x + threadIdx.x;
    const int NW = 3 * PQ * HQ;          // 589824
    const int NC = HQ * 2 * PQ;          // 393216
    if (idx < NW) {
        int n = idx / HQ;
        int h = idx % HQ;
        float v;
        if (n < PQ)            v = W_dt[(size_t)h * PQ + n];
        else if (n < 2 * PQ)   v = B_re[(size_t)(n - PQ) * HQ + h];
        else                   v = B_im[(size_t)(n - 2 * PQ) * HQ + h];
        g_Wh[idx] = __float2half_rn(v);
    } else if (idx < NW + NC) {
        int j = idx - NW;
        int h = j / (2 * PQ);
        int k = j % (2 * PQ);
        float v = (k < PQ) ? C_re[(size_t)h * PQ + k] : -C_im[(size_t)h * PQ + (k - PQ)];
        g_Ch[j] = __float2half_rn(v);
    }
}

// ---------------- fp16 mma.sync GEMM (R15-verified, unchanged) ---------------
template<bool EPI>
__global__ __launch_bounds__(256, 2)
void gemm_h(const __half* __restrict__ A, const __half* __restrict__ Bt,
            void* __restrict__ Cout, int M, int N, int K,
            const float* __restrict__ Dv, const __half* __restrict__ U) {
    extern __shared__ char smem[];
    const uint32_t sb = smem_u32(smem);
    const int tid = threadIdx.x;
    const int wid = tid >> 5, lane = tid & 31;
    const int m0 = blockIdx.y * BM, n0 = blockIdx.x * BN;
    const int wm = wid >> 2, wn = wid & 3;     // 2 x 4 warp grid
    const int NS = K / KC;

    const int t7 = lane & 7, jq = lane >> 3;
    const uint32_t swmask = (uint32_t)t7 << 4;
    const int rowA = (jq & 1) * 8 + t7;
    const int kgA  = jq >> 1;
    const int rowB = (jq >> 1) * 8 + t7;
    const int kgB  = jq & 1;

    auto stage = [&](int s) {
        uint32_t buf = sb + (uint32_t)(s % NSTG) * STG;
        int kt = s * KC;
#pragma unroll
        for (int i = 0; i < 4; i++) {
            int c = tid + i * 256;
            int r = c >> 3, k8 = c & 7;
            uint32_t off = (uint32_t)(k8 * 16) ^ ((uint32_t)(r & 7) << 4);
            cp16(buf + (uint32_t)r * 128 + off, A + (size_t)(m0 + r) * K + kt + k8 * 8);
        }
#pragma unroll
        for (int i = 0; i < 4; i++) {
            int c = tid + i * 256;
            int r = c >> 3, k8 = c & 7;
            uint32_t off = (uint32_t)(k8 * 16) ^ ((uint32_t)(r & 7) << 4);
            cp16(buf + ASZ + (uint32_t)r * 128 + off, Bt + (size_t)(n0 + r) * K + kt + k8 * 8);
        }
        CP_COMMIT();
    };

    float acc[4][4][4];
#pragma unroll
    for (int i = 0; i < 4; i++)
#pragma unroll
        for (int j = 0; j < 4; j++)
#pragma unroll
            for (int v = 0; v < 4; v++) acc[i][j][v] = 0.f;

    stage(0);
    stage(1);

    for (int s = 0; s < NS; s++) {
        if (s < NS - 1) { CP_WAIT(1); } else { CP_WAIT(0); }
        __syncthreads();
        if (s + NSTG - 1 < NS) stage(s + NSTG - 1);
        uint32_t ab = sb + (uint32_t)(s % NSTG) * STG;
        uint32_t bb = ab + ASZ;
#pragma unroll
        for (int q = 0; q < 4; q++) {
            uint32_t af[4][4];
#pragma unroll
            for (int i = 0; i < 4; i++) {
                uint32_t ad = ab + (uint32_t)((wm * 64 + i * 16 + rowA) * 128)
                                 + ((uint32_t)(q * 32 + kgA * 16) ^ swmask);
                LDSM_X4(af[i][0], af[i][1], af[i][2], af[i][3], ad);
            }
            uint32_t bf[4][2];
#pragma unroll
            for (int np = 0; np < 2; np++) {
                uint32_t bd = bb + (uint32_t)((wn * 32 + np * 16 + rowB) * 128)
                                 + ((uint32_t)(q * 32 + kgB * 16) ^ swmask);
                LDSM_X4(bf[np*2][0], bf[np*2][1], bf[np*2+1][0], bf[np*2+1][1], bd);
            }
#pragma unroll
            for (int i = 0; i < 4; i++)
#pragma unroll
                for (int jn = 0; jn < 4; jn++)
                    MMA_F16(acc[i][jn], af[i], bf[jn]);
        }
    }

    const int gr = lane >> 2, gc = (lane & 3) * 2;
#pragma unroll
    for (int i = 0; i < 4; i++) {
        int r = m0 + wm * 64 + i * 16 + gr;
#pragma unroll
        for (int jn = 0; jn < 4; jn++) {
            int c = n0 + wn * 32 + jn * 8 + gc;
            if (EPI) {
                float* C = (float*)Cout;
                float2 v0 = make_float2(acc[i][jn][0], acc[i][jn][1]);
                float2 v1 = make_float2(acc[i][jn][2], acc[i][jn][3]);
                float2 dd = *(const float2*)(Dv + c);
                __half2 uh0 = *(const __half2*)(U + (size_t)r * N + c);
                __half2 uh1 = *(const __half2*)(U + (size_t)(r + 8) * N + c);
                float2 u0 = __half22float2(uh0), u1 = __half22float2(uh1);
                v0.x = fmaf(dd.x, u0.x, v0.x); v0.y = fmaf(dd.y, u0.y, v0.y);
                v1.x = fmaf(dd.x, u1.x, v1.x); v1.y = fmaf(dd.y, u1.y, v1.y);
                *(float2*)(C + (size_t)r * N + c)       = v0;
                *(float2*)(C + (size_t)(r + 8) * N + c) = v1;
            } else {
                __half* C = (__half*)Cout;
                *(__half2*)(C + (size_t)r * N + c) =
                    __floats2half2_rn(acc[i][jn][0], acc[i][jn][1]);
                *(__half2*)(C + (size_t)(r + 8) * N + c) =
                    __floats2half2_rn(acc[i][jn][2], acc[i][jn][3]);
            }
        }
    }
}

// ---------------- fused scan: one block per channel-pair ---------------------
struct Elt { float a11, a12, a21, a22, b1r, b1i, b2r, b2i; };
__device__ __forceinline__ Elt elt_id() {
    return Elt{1.f, 0.f, 0.f, 1.f, 0.f, 0.f, 0.f, 0.f};
}
// compose: i earlier, j later (matches reference _binop)
__device__ __forceinline__ Elt compose(const Elt& i, const Elt& j) {
    Elt r;
    r.a11 = j.a11 * i.a11 + j.a12 * i.a21;
    r.a12 = j.a11 * i.a12 + j.a12 * i.a22;
    r.a21 = j.a21 * i.a11 + j.a22 * i.a21;
    r.a22 = j.a21 * i.a12 + j.a22 * i.a22;
    r.b1r = j.a11 * i.b1r + j.a12 * i.b2r + j.b1r;
    r.b1i = j.a11 * i.b1i + j.a12 * i.b2i + j.b1i;
    r.b2r = j.a21 * i.b1r + j.a22 * i.b2r + j.b2r;
    r.b2i = j.a21 * i.b1i + j.a22 * i.b2i + j.b2i;
    return r;
}
__device__ __forceinline__ Elt shfl_up_elt(const Elt& e, int off) {
    Elt r;
    r.a11 = __shfl_up_sync(0xffffffffu, e.a11, off);
    r.a12 = __shfl_up_sync(0xffffffffu, e.a12, off);
    r.a21 = __shfl_up_sync(0xffffffffu, e.a21, off);
    r.a22 = __shfl_up_sync(0xffffffffu, e.a22, off);
    r.b1r = __shfl_up_sync(0xffffffffu, e.b1r, off);
    r.b1i = __shfl_up_sync(0xffffffffu, e.b1i, off);
    r.b2r = __shfl_up_sync(0xffffffffu, e.b2r, off);
    r.b2i = __shfl_up_sync(0xffffffffu, e.b2i, off);
    return r;
}
__device__ __forceinline__ void step_ch(float logit, float bur, float bui, float Aa,
                                        float& s1r, float& s1i, float& s2r, float& s2i) {
    float dt  = 1.f / (1.f + __expf(-logit));
    float dtA = dt * Aa;
    float S   = 1.f / (1.f + dt * dtA);
    float M11 = 1.f - dt * dtA * S;
    float M12 = -dtA * S;
    float M21 = dt * S;
    float M22 = S;
    float f1  = M11 * dt;
    float f2  = M21 * dt;
    float n1r = M11 * s1r + M12 * s2r + f1 * bur;
    float n1i = M11 * s1i + M12 * s2i + f1 * bui;
    float n2r = M21 * s1r + M22 * s2r + f2 * bur;
    float n2i = M21 * s1i + M22 * s2i + f2 * bui;
    s1r = n1r; s1i = n1i; s2r = n2r; s2i = n2i;
}
__device__ __forceinline__ void stepM_ch(float logit, float bur, float bui, float Aa,
                                         Elt& e) {
    float dt  = 1.f / (1.f + __expf(-logit));
    float dtA = dt * Aa;
    float S   = 1.f / (1.f + dt * dtA);
    float M11 = 1.f - dt * dtA * S;
    float M12 = -dtA * S;
    float M21 = dt * S;
    float M22 = S;
    float f1  = M11 * dt;
    float f2  = M21 * dt;
    float n11 = M11 * e.a11 + M12 * e.a21, n12 = M11 * e.a12 + M12 * e.a22;
    float n21 = M21 * e.a11 + M22 * e.a21, n22 = M21 * e.a12 + M22 * e.a22;
    e.a11 = n11; e.a12 = n12; e.a21 = n21; e.a22 = n22;
    float nb1r = M11 * e.b1r + M12 * e.b2r + f1 * bur;
    float nb1i = M11 * e.b1i + M12 * e.b2i + f1 * bui;
    float nb2r = M21 * e.b1r + M22 * e.b2r + f2 * bur;
    float nb2i = M21 * e.b1i + M22 * e.b2i + f2 * bui;
    e.b1r = nb1r; e.b1i = nb1i; e.b2r = nb2r; e.b2i = nb2i;
}

// grid = BQ * (PQ/2) = 1024 blocks, block = NCHUNK = 128 threads.
// Thread t owns chunk t (LC=32 timesteps) of its block's channel pair.
__global__ __launch_bounds__(128)
void scan_fused(const float* __restrict__ A_diag) {
    __shared__ Elt s_wtot[2][4];

    int bp = blockIdx.x;
    int pp = bp & 127;                 // channel-pair index
    int b  = bp >> 7;                  // batch
    int t  = threadIdx.x;              // chunk index 0..127
    int w  = t >> 5, lane = t & 31;
    int p0 = pp * 2;
    float2 Aa = make_float2(fmaxf(A_diag[p0], 0.f), fmaxf(A_diag[p0 + 1], 0.f));

    int row0 = b * LQ + t * LC;
    size_t base = (size_t)row0 * (3 * PQ);
    const __half2* yr = (const __half2*)(g_Yh + base);

    // ---- phase 1: local compose over LC steps for both channels ----
    Elt e0 = elt_id(), e1 = elt_id();
    {
        __half2 lg = yr[pp], br = yr[128 + pp], bi = yr[256 + pp];
        for (int i = 0; i < LC; i++) {
            __half2 nlg, nbr, nbi;
            if (i + 1 < LC) {
                const __half2* yn = yr + (size_t)(i + 1) * 384;
                nlg = yn[pp]; nbr = yn[128 + pp]; nbi = yn[256 + pp];
            }
            float2 l = __half22float2(lg), r = __half22float2(br), m = __half22float2(bi);
            stepM_ch(l.x, r.x, m.x, Aa.x, e0);
            stepM_ch(l.y, r.y, m.y, Aa.y, e1);
            lg = nlg; br = nbr; bi = nbi;
        }
    }

    // ---- phase 2: block exclusive scan over chunk summaries ----
    Elt inc0 = e0, inc1 = e1;
#pragma unroll
    for (int off = 1; off < 32; off <<= 1) {
        Elt p0e = shfl_up_elt(inc0, off);
        Elt p1e = shfl_up_elt(inc1, off);
        if (lane >= off) { inc0 = compose(p0e, inc0); inc1 = compose(p1e, inc1); }
    }
    Elt lex0 = shfl_up_elt(inc0, 1);
    Elt lex1 = shfl_up_elt(inc1, 1);
    if (lane == 0) { lex0 = elt_id(); lex1 = elt_id(); }
    if (lane == 31) { s_wtot[0][w] = inc0; s_wtot[1][w] = inc1; }
    __syncthreads();
    Elt wpre0 = elt_id(), wpre1 = elt_id();
    for (int ww = 0; ww < w; ww++) {
        wpre0 = compose(wpre0, s_wtot[0][ww]);
        wpre1 = compose(wpre1, s_wtot[1][ww]);
    }
    Elt ex0 = compose(wpre0, lex0);
    Elt ex1 = compose(wpre1, lex1);
    // carry entering this chunk = b-vector of exclusive prefix (initial state 0)
    float s1r[2] = {ex0.b1r, ex1.b1r}, s1i[2] = {ex0.b1i, ex1.b1i};
    float s2r[2] = {ex0.b2r, ex1.b2r}, s2i[2] = {ex0.b2i, ex1.b2i};

    // ---- phase 3: replay, writing x ----
    {
        __half2 lg = yr[pp], br = yr[128 + pp], bi = yr[256 + pp];
        for (int i = 0; i < LC; i++) {
            __half2 nlg, nbr, nbi;
            if (i + 1 < LC) {
                const __half2* yn = yr + (size_t)(i + 1) * 384;
                nlg = yn[pp]; nbr = yn[128 + pp]; nbi = yn[256 + pp];
            }
            float2 l = __half22float2(lg), r = __half22float2(br), m = __half22float2(bi);
            step_ch(l.x, r.x, m.x, Aa.x, s1r[0], s1i[0], s2r[0], s2i[0]);
            step_ch(l.y, r.y, m.y, Aa.y, s1r[1], s1i[1], s2r[1], s2i[1]);
            size_t xrow = (size_t)(row0 + i) * (2 * PQ);
            *(__half2*)(g_Xh + xrow + p0)      = __floats2half2_rn(s2r[0], s2r[1]);
            *(__half2*)(g_Xh + xrow + PQ + p0) = __floats2half2_rn(s2i[0], s2i[1]);
            lg = nlg; br = nbr; bi = nbi;
        }
    }
}

// ---------------- launch ----------------------------------------------------
extern "C" void kernel_launch(void* const* d_in, const int* in_sizes, int n_in,
                              void* d_out, int out_size) {
    const float* u      = (const float*)d_in[0];
    const float* A_diag = (const float*)d_in[1];
    const float* B_re   = (const float*)d_in[2];
    const float* B_im   = (const float*)d_in[3];
    const float* C_re   = (const float*)d_in[4];
    const float* C_im   = (const float*)d_in[5];
    const float* D      = (const float*)d_in[6];
    const float* W_dt   = (const float*)d_in[7];
    float* out = (float*)d_out;

    __half* Yh = nullptr; cudaGetSymbolAddress((void**)&Yh, g_Yh);
    __half* Xh = nullptr; cudaGetSymbolAddress((void**)&Xh, g_Xh);
    __half* Wh = nullptr; cudaGetSymbolAddress((void**)&Wh, g_Wh);
    __half* Ch = nullptr; cudaGetSymbolAddress((void**)&Ch, g_Ch);
    __half* uh = nullptr; cudaGetSymbolAddress((void**)&uh, g_uh);

    cudaFuncSetAttribute(gemm_h<false>, cudaFuncAttributeMaxDynamicSharedMemorySize, GSMEM);
    cudaFuncSetAttribute(gemm_h<true>,  cudaFuncAttributeMaxDynamicSharedMemorySize, GSMEM);

    {
        int total = 3 * PQ * HQ + HQ * 2 * PQ;
        prep_weights<<<(total + 255) / 256, 256>>>(W_dt, B_re, B_im, C_re, C_im);
    }
    {
        int n4 = ROWS * HQ / 4;
        convert_u<<<(n4 + 255) / 256, 256>>>((const float4*)u, (__half2*)uh, n4);
    }

    // GEMM1: Yh[32768,768] = uh @ Wh^T  (fp16 out)
    {
        dim3 grid(3 * PQ / BN, ROWS / BM);
        gemm_h<false><<<grid, 256, GSMEM>>>(uh, Wh, Yh, ROWS, 3 * PQ, HQ, nullptr, nullptr);
    }

    // Fused scan: 1024 blocks x 128 threads
    scan_fused<<<BQ * (PQ / 2), NCHUNK>>>(A_diag);

    // GEMM2: out = Xh @ Ch^T + D .* u  (fp32 out, u via fp16 copy)
    {
        dim3 grid(HQ / BN, ROWS / BM);
        gemm_h<true><<<grid, 256, GSMEM>>>(Xh, Ch, out, ROWS, HQ, 2 * PQ, D, uh);
    }
}

// round 17
// speedup vs baseline: 1.3183x; 1.3183x over previous
#include <cuda_runtime.h>
#include <cuda_fp16.h>
#include <cstdint>

// Problem dims (fixed per reference)
#define BQ 8
#define LQ 4096
#define HQ 768
#define PQ 256
#define ROWS (BQ*LQ)        // 32768
#define LC 32               // scan chunk length
#define NCHUNK (LQ/LC)      // 128

// GEMM tiling (fp16 operands) — R12/R15-verified: CTA 128x128, warps 2x4 of 64x32
#define BM 128
#define BN 128
#define KC 64               // halfs per stage-row = 128 bytes
#define NSTG 3
#define ASZ (BM*KC*2)       // 16 KB
#define BSZ (BN*KC*2)       // 16 KB
#define STG (ASZ+BSZ)       // 32 KB
#define GSMEM (NSTG*STG)    // 96 KB

// ---------------- scratch (__device__ globals) ------------------------------
__device__ __half g_Wh[3*PQ * HQ];               // [n=768][k=768] K-major fp16
__device__ __half g_Ch[HQ * 2*PQ];               // [n=768][k=512] K-major fp16
__device__ __half g_uh[(size_t)ROWS * HQ];       // fp16 copy of u
__device__ __half g_Yh[(size_t)ROWS * 3 * PQ];   // dt-logit | Bu_re | Bu_im (fp16)
__device__ __half g_Xh[(size_t)ROWS * 2 * PQ];   // x_re | x_im (fp16)
__device__ float  g_chunk[BQ * PQ * NCHUNK * 8];
__device__ float  g_carry[BQ * PQ * NCHUNK * 4];

// ---------------- helpers ---------------------------------------------------
__device__ __forceinline__ uint32_t smem_u32(const void* p) {
    uint32_t a;
    asm("{ .reg .u64 t; cvta.to.shared.u64 t, %1; cvt.u32.u64 %0, t; }" : "=r"(a) : "l"(p));
    return a;
}
__device__ __forceinline__ void cp16(uint32_t smem, const void* gmem) {
    asm volatile("cp.async.cg.shared.global [%0], [%1], 16;" :: "r"(smem), "l"(gmem) : "memory");
}
#define CP_COMMIT()  asm volatile("cp.async.commit_group;" ::: "memory")
#define CP_WAIT(n)   asm volatile("cp.async.wait_group %0;" :: "n"(n) : "memory")

#define LDSM_X4(r0,r1,r2,r3,addr) \
    asm volatile("ldmatrix.sync.aligned.m8n8.x4.shared.b16 {%0,%1,%2,%3}, [%4];" \
        : "=r"(r0),"=r"(r1),"=r"(r2),"=r"(r3) : "r"(addr))

#define MMA_F16(c, a, b) \
    asm volatile("mma.sync.aligned.m16n8k16.row.col.f32.f16.f16.f32 " \
        "{%0,%1,%2,%3}, {%4,%5,%6,%7}, {%8,%9}, {%0,%1,%2,%3};" \
        : "+f"((c)[0]),"+f"((c)[1]),"+f"((c)[2]),"+f"((c)[3]) \
        : "r"((a)[0]),"r"((a)[1]),"r"((a)[2]),"r"((a)[3]), "r"((b)[0]),"r"((b)[1]))

// ---------------- prep kernels ----------------------------------------------
// 8 floats per thread
__global__ void convert_u(const float4* __restrict__ in, __half2* __restrict__ out, int n8) {
    int i = blockIdx.x * blockDim.x + threadIdx.x;
    if (i >= n8) return;
    float4 v0 = in[2*i], v1 = in[2*i+1];
    out[4*i+0] = __floats2half2_rn(v0.x, v0.y);
    out[4*i+1] = __floats2half2_rn(v0.z, v0.w);
    out[4*i+2] = __floats2half2_rn(v1.x, v1.y);
    out[4*i+3] = __floats2half2_rn(v1.z, v1.w);
}

// merged weight prep: first 3*PQ*HQ elements -> g_Wh, rest -> g_Ch
__global__ void prep_weights(const float* __restrict__ W_dt,
                             const float* __restrict__ B_re,
                             const float* __restrict__ B_im,
                             const float* __restrict__ C_re,
                             const float* __restrict__ C_im) {
    int idx = blockIdx.x * blockDim.x + threadIdx.x;
    const int NW = 3 * PQ * HQ;          // 589824
    const int NC = HQ * 2 * PQ;          // 393216
    if (idx < NW) {
        int n = idx / HQ;
        int h = idx % HQ;
        float v;
        if (n < PQ)            v = W_dt[(size_t)h * PQ + n];
        else if (n < 2 * PQ)   v = B_re[(size_t)(n - PQ) * HQ + h];
        else                   v = B_im[(size_t)(n - 2 * PQ) * HQ + h];
        g_Wh[idx] = __float2half_rn(v);
    } else if (idx < NW + NC) {
        int j = idx - NW;
        int h = j / (2 * PQ);
        int k = j % (2 * PQ);
        float v = (k < PQ) ? C_re[(size_t)h * PQ + k] : -C_im[(size_t)h * PQ + (k - PQ)];
        g_Ch[j] = __float2half_rn(v);
    }
}

// ---------------- fp16 mma.sync GEMM (R15-verified, unchanged) ---------------
template<bool EPI>
__global__ __launch_bounds__(256, 2)
void gemm_h(const __half* __restrict__ A, const __half* __restrict__ Bt,
            void* __restrict__ Cout, int M, int N, int K,
            const float* __restrict__ Dv, const __half* __restrict__ U) {
    extern __shared__ char smem[];
    const uint32_t sb = smem_u32(smem);
    const int tid = threadIdx.x;
    const int wid = tid >> 5, lane = tid & 31;
    const int m0 = blockIdx.y * BM, n0 = blockIdx.x * BN;
    const int wm = wid >> 2, wn = wid & 3;     // 2 x 4 warp grid
    const int NS = K / KC;

    const int t7 = lane & 7, jq = lane >> 3;
    const uint32_t swmask = (uint32_t)t7 << 4;
    const int rowA = (jq & 1) * 8 + t7;
    const int kgA  = jq >> 1;
    const int rowB = (jq >> 1) * 8 + t7;
    const int kgB  = jq & 1;

    auto stage = [&](int s) {
        uint32_t buf = sb + (uint32_t)(s % NSTG) * STG;
        int kt = s * KC;
#pragma unroll
        for (int i = 0; i < 4; i++) {
            int c = tid + i * 256;
            int r = c >> 3, k8 = c & 7;
            uint32_t off = (uint32_t)(k8 * 16) ^ ((uint32_t)(r & 7) << 4);
            cp16(buf + (uint32_t)r * 128 + off, A + (size_t)(m0 + r) * K + kt + k8 * 8);
        }
#pragma unroll
        for (int i = 0; i < 4; i++) {
            int c = tid + i * 256;
            int r = c >> 3, k8 = c & 7;
            uint32_t off = (uint32_t)(k8 * 16) ^ ((uint32_t)(r & 7) << 4);
            cp16(buf + ASZ + (uint32_t)r * 128 + off, Bt + (size_t)(n0 + r) * K + kt + k8 * 8);
        }
        CP_COMMIT();
    };

    float acc[4][4][4];
#pragma unroll
    for (int i = 0; i < 4; i++)
#pragma unroll
        for (int j = 0; j < 4; j++)
#pragma unroll
            for (int v = 0; v < 4; v++) acc[i][j][v] = 0.f;

    stage(0);
    stage(1);

    for (int s = 0; s < NS; s++) {
        if (s < NS - 1) { CP_WAIT(1); } else { CP_WAIT(0); }
        __syncthreads();
        // Prefetch early: buffer (s+2)%3 == (s-1)%3; readers passed the barrier.
        if (s + NSTG - 1 < NS) stage(s + NSTG - 1);
        uint32_t ab = sb + (uint32_t)(s % NSTG) * STG;
        uint32_t bb = ab + ASZ;
#pragma unroll
        for (int q = 0; q < 4; q++) {
            uint32_t af[4][4];
#pragma unroll
            for (int i = 0; i < 4; i++) {
                uint32_t ad = ab + (uint32_t)((wm * 64 + i * 16 + rowA) * 128)
                                 + ((uint32_t)(q * 32 + kgA * 16) ^ swmask);
                LDSM_X4(af[i][0], af[i][1], af[i][2], af[i][3], ad);
            }
            uint32_t bf[4][2];
#pragma unroll
            for (int np = 0; np < 2; np++) {
                uint32_t bd = bb + (uint32_t)((wn * 32 + np * 16 + rowB) * 128)
                                 + ((uint32_t)(q * 32 + kgB * 16) ^ swmask);
                LDSM_X4(bf[np*2][0], bf[np*2][1], bf[np*2+1][0], bf[np*2+1][1], bd);
            }
#pragma unroll
            for (int i = 0; i < 4; i++)
#pragma unroll
                for (int jn = 0; jn < 4; jn++)
                    MMA_F16(acc[i][jn], af[i], bf[jn]);
        }
    }

    const int gr = lane >> 2, gc = (lane & 3) * 2;
#pragma unroll
    for (int i = 0; i < 4; i++) {
        int r = m0 + wm * 64 + i * 16 + gr;
#pragma unroll
        for (int jn = 0; jn < 4; jn++) {
            int c = n0 + wn * 32 + jn * 8 + gc;
            if (EPI) {
                float* C = (float*)Cout;
                float2 v0 = make_float2(acc[i][jn][0], acc[i][jn][1]);
                float2 v1 = make_float2(acc[i][jn][2], acc[i][jn][3]);
                float2 dd = *(const float2*)(Dv + c);
                __half2 uh0 = *(const __half2*)(U + (size_t)r * N + c);
                __half2 uh1 = *(const __half2*)(U + (size_t)(r + 8) * N + c);
                float2 u0 = __half22float2(uh0), u1 = __half22float2(uh1);
                v0.x = fmaf(dd.x, u0.x, v0.x); v0.y = fmaf(dd.y, u0.y, v0.y);
                v1.x = fmaf(dd.x, u1.x, v1.x); v1.y = fmaf(dd.y, u1.y, v1.y);
                *(float2*)(C + (size_t)r * N + c)       = v0;
                *(float2*)(C + (size_t)(r + 8) * N + c) = v1;
            } else {
                __half* C = (__half*)Cout;
                *(__half2*)(C + (size_t)r * N + c) =
                    __floats2half2_rn(acc[i][jn][0], acc[i][jn][1]);
                *(__half2*)(C + (size_t)(r + 8) * N + c) =
                    __floats2half2_rn(acc[i][jn][2], acc[i][jn][3]);
            }
        }
    }
}

// ---------------- scan (R15-verified: 3-pass, paired channels, pipelined) ---
__device__ __forceinline__ void step_ch(float logit, float bur, float bui, float Aa,
                                        float& s1r, float& s1i, float& s2r, float& s2i) {
    float dt  = 1.f / (1.f + __expf(-logit));
    float dtA = dt * Aa;
    float S   = 1.f / (1.f + dt * dtA);
    float M11 = 1.f - dt * dtA * S;
    float M12 = -dtA * S;
    float M21 = dt * S;
    float M22 = S;
    float f1  = M11 * dt;
    float f2  = M21 * dt;
    float n1r = M11 * s1r + M12 * s2r + f1 * bur;
    float n1i = M11 * s1i + M12 * s2i + f1 * bui;
    float n2r = M21 * s1r + M22 * s2r + f2 * bur;
    float n2i = M21 * s1i + M22 * s2i + f2 * bui;
    s1r = n1r; s1i = n1i; s2r = n2r; s2i = n2i;
}
__device__ __forceinline__ void stepM_ch(float logit, float bur, float bui, float Aa,
                                         float& a11, float& a12, float& a21, float& a22,
                                         float& b1r, float& b1i, float& b2r, float& b2i) {
    float dt  = 1.f / (1.f + __expf(-logit));
    float dtA = dt * Aa;
    float S   = 1.f / (1.f + dt * dtA);
    float M11 = 1.f - dt * dtA * S;
    float M12 = -dtA * S;
    float M21 = dt * S;
    float M22 = S;
    float f1  = M11 * dt;
    float f2  = M21 * dt;
    float n11 = M11 * a11 + M12 * a21, n12 = M11 * a12 + M12 * a22;
    float n21 = M21 * a11 + M22 * a21, n22 = M21 * a12 + M22 * a22;
    a11 = n11; a12 = n12; a21 = n21; a22 = n22;
    float nb1r = M11 * b1r + M12 * b2r + f1 * bur;
    float nb1i = M11 * b1i + M12 * b2i + f1 * bui;
    float nb2r = M21 * b1r + M22 * b2r + f2 * bur;
    float nb2i = M21 * b1i + M22 * b2i + f2 * bui;
    b1r = nb1r; b1i = nb1i; b2r = nb2r; b2i = nb2i;
}

// threads: B * (P/2) * NCHUNK = 8*128*128 = 131072
__global__ void scan_passA(const float* __restrict__ A_diag) {
    int t = blockIdx.x * blockDim.x + threadIdx.x;
    int pp = t & 127;                 // channel pair index
    int ck = (t >> 7) & (NCHUNK - 1);
    int b  = t >> 14;
    int p0 = pp * 2;
    float2 Aa = make_float2(fmaxf(A_diag[p0], 0.f), fmaxf(A_diag[p0 + 1], 0.f));
    float a11[2] = {1.f, 1.f}, a12[2] = {0.f, 0.f}, a21[2] = {0.f, 0.f}, a22[2] = {1.f, 1.f};
    float b1r[2] = {0.f, 0.f}, b1i[2] = {0.f, 0.f}, b2r[2] = {0.f, 0.f}, b2i[2] = {0.f, 0.f};
    size_t base = (size_t)(b * LQ + ck * LC) * (3 * PQ);
    const __half2* yr = (const __half2*)(g_Yh + base);
    __half2 lg = yr[pp], br = yr[128 + pp], bi = yr[256 + pp];
    for (int i = 0; i < LC; i++) {
        __half2 nlg, nbr, nbi;
        if (i + 1 < LC) {
            const __half2* yn = yr + (size_t)(i + 1) * 384;
            nlg = yn[pp]; nbr = yn[128 + pp]; nbi = yn[256 + pp];
        }
        float2 l = __half22float2(lg), r = __half22float2(br), m = __half22float2(bi);
        stepM_ch(l.x, r.x, m.x, Aa.x, a11[0], a12[0], a21[0], a22[0],
                 b1r[0], b1i[0], b2r[0], b2i[0]);
        stepM_ch(l.y, r.y, m.y, Aa.y, a11[1], a12[1], a21[1], a22[1],
                 b1r[1], b1i[1], b2r[1], b2i[1]);
        lg = nlg; br = nbr; bi = nbi;
    }
#pragma unroll
    for (int c = 0; c < 2; c++) {
        size_t cidx = ((size_t)(b * PQ + p0 + c) * NCHUNK + ck) * 8;
        g_chunk[cidx + 0] = a11[c]; g_chunk[cidx + 1] = a12[c];
        g_chunk[cidx + 2] = a21[c]; g_chunk[cidx + 3] = a22[c];
        g_chunk[cidx + 4] = b1r[c]; g_chunk[cidx + 5] = b1i[c];
        g_chunk[cidx + 6] = b2r[c]; g_chunk[cidx + 7] = b2i[c];
    }
}

// ---------------- passB: warp-per-channel Kogge-Stone over 128 chunks -------
struct Elt { float a11, a12, a21, a22, b1r, b1i, b2r, b2i; };
__device__ __forceinline__ Elt compose(const Elt& i, const Elt& j) {
    Elt r;
    r.a11 = j.a11 * i.a11 + j.a12 * i.a21;
    r.a12 = j.a11 * i.a12 + j.a12 * i.a22;
    r.a21 = j.a21 * i.a11 + j.a22 * i.a21;
    r.a22 = j.a21 * i.a12 + j.a22 * i.a22;
    r.b1r = j.a11 * i.b1r + j.a12 * i.b2r + j.b1r;
    r.b1i = j.a11 * i.b1i + j.a12 * i.b2i + j.b1i;
    r.b2r = j.a21 * i.b1r + j.a22 * i.b2r + j.b2r;
    r.b2i = j.a21 * i.b1i + j.a22 * i.b2i + j.b2i;
    return r;
}
__device__ __forceinline__ Elt shfl_up_elt(const Elt& e, int off) {
    Elt r;
    r.a11 = __shfl_up_sync(0xffffffffu, e.a11, off);
    r.a12 = __shfl_up_sync(0xffffffffu, e.a12, off);
    r.a21 = __shfl_up_sync(0xffffffffu, e.a21, off);
    r.a22 = __shfl_up_sync(0xffffffffu, e.a22, off);
    r.b1r = __shfl_up_sync(0xffffffffu, e.b1r, off);
    r.b1i = __shfl_up_sync(0xffffffffu, e.b1i, off);
    r.b2r = __shfl_up_sync(0xffffffffu, e.b2r, off);
    r.b2i = __shfl_up_sync(0xffffffffu, e.b2i, off);
    return r;
}
__device__ __forceinline__ float4 apply_elt(const Elt& e, float4 s) {
    return make_float4(
        e.a11 * s.x + e.a12 * s.z + e.b1r,
        e.a11 * s.y + e.a12 * s.w + e.b1i,
        e.a21 * s.x + e.a22 * s.z + e.b2r,
        e.a21 * s.y + e.a22 * s.w + e.b2i);
}

__global__ void scan_passB() {
    int gtid = blockIdx.x * blockDim.x + threadIdx.x;
    int ch = gtid >> 5;                 // channel 0..2047
    int lane = gtid & 31;
    if (ch >= BQ * PQ) return;
    size_t cb = (size_t)ch * NCHUNK;
    const float4* cp = (const float4*)(g_chunk + (cb + 4 * lane) * 8);
    Elt c[4];
#pragma unroll
    for (int k = 0; k < 4; k++) {
        float4 qa = cp[2 * k], qb = cp[2 * k + 1];
        c[k] = Elt{qa.x, qa.y, qa.z, qa.w, qb.x, qb.y, qb.z, qb.w};
    }
    Elt c01 = compose(c[0], c[1]);
    Elt inc = compose(c01, compose(c[2], c[3]));
#pragma unroll
    for (int off = 1; off < 32; off <<= 1) {
        Elt prev = shfl_up_elt(inc, off);
        if (lane >= off) inc = compose(prev, inc);
    }
    Elt excl = shfl_up_elt(inc, 1);
    if (lane == 0) excl = Elt{1.f, 0.f, 0.f, 1.f, 0.f, 0.f, 0.f, 0.f};
    float4 s = make_float4(excl.b1r, excl.b1i, excl.b2r, excl.b2i);
    float4* w = (float4*)(g_carry + (cb + 4 * lane) * 4);
    w[0] = s;
    s = apply_elt(c[0], s); w[1] = s;
    s = apply_elt(c[1], s); w[2] = s;
    s = apply_elt(c[2], s); w[3] = s;
}

__global__ void scan_passC(const float* __restrict__ A_diag) {
    int t = blockIdx.x * blockDim.x + threadIdx.x;
    int pp = t & 127;
    int ck = (t >> 7) & (NCHUNK - 1);
    int b  = t >> 14;
    int p0 = pp * 2;
    float2 Aa = make_float2(fmaxf(A_diag[p0], 0.f), fmaxf(A_diag[p0 + 1], 0.f));
    float s1r[2], s1i[2], s2r[2], s2i[2];
#pragma unroll
    for (int c = 0; c < 2; c++) {
        size_t cidx = ((size_t)(b * PQ + p0 + c) * NCHUNK + ck) * 4;
        s1r[c] = g_carry[cidx + 0]; s1i[c] = g_carry[cidx + 1];
        s2r[c] = g_carry[cidx + 2]; s2i[c] = g_carry[cidx + 3];
    }
    int row0 = b * LQ + ck * LC;
    size_t base = (size_t)row0 * (3 * PQ);
    const __half2* yr = (const __half2*)(g_Yh + base);
    __half2 lg = yr[pp], br = yr[128 + pp], bi = yr[256 + pp];
    for (int i = 0; i < LC; i++) {
        __half2 nlg, nbr, nbi;
        if (i + 1 < LC) {
            const __half2* yn = yr + (size_t)(i + 1) * 384;
            nlg = yn[pp]; nbr = yn[128 + pp]; nbi = yn[256 + pp];
        }
        float2 l = __half22float2(lg), r = __half22float2(br), m = __half22float2(bi);
        step_ch(l.x, r.x, m.x, Aa.x, s1r[0], s1i[0], s2r[0], s2i[0]);
        step_ch(l.y, r.y, m.y, Aa.y, s1r[1], s1i[1], s2r[1], s2i[1]);
        size_t xrow = (size_t)(row0 + i) * (2 * PQ);
        *(__half2*)(g_Xh + xrow + p0)      = __floats2half2_rn(s2r[0], s2r[1]);
        *(__half2*)(g_Xh + xrow + PQ + p0) = __floats2half2_rn(s2i[0], s2i[1]);
        lg = nlg; br = nbr; bi = nbi;
    }
}

// ---------------- launch ----------------------------------------------------
extern "C" void kernel_launch(void* const* d_in, const int* in_sizes, int n_in,
                              void* d_out, int out_size) {
    const float* u      = (const float*)d_in[0];
    const float* A_diag = (const float*)d_in[1];
    const float* B_re   = (const float*)d_in[2];
    const float* B_im   = (const float*)d_in[3];
    const float* C_re   = (const float*)d_in[4];
    const float* C_im   = (const float*)d_in[5];
    const float* D      = (const float*)d_in[6];
    const float* W_dt   = (const float*)d_in[7];
    float* out = (float*)d_out;

    __half* Yh = nullptr; cudaGetSymbolAddress((void**)&Yh, g_Yh);
    __half* Xh = nullptr; cudaGetSymbolAddress((void**)&Xh, g_Xh);
    __half* Wh = nullptr; cudaGetSymbolAddress((void**)&Wh, g_Wh);
    __half* Ch = nullptr; cudaGetSymbolAddress((void**)&Ch, g_Ch);
    __half* uh = nullptr; cudaGetSymbolAddress((void**)&uh, g_uh);

    cudaFuncSetAttribute(gemm_h<false>, cudaFuncAttributeMaxDynamicSharedMemorySize, GSMEM);
    cudaFuncSetAttribute(gemm_h<true>,  cudaFuncAttributeMaxDynamicSharedMemorySize, GSMEM);

    {
        int total = 3 * PQ * HQ + HQ * 2 * PQ;
        prep_weights<<<(total + 255) / 256, 256>>>(W_dt, B_re, B_im, C_re, C_im);
    }
    {
        int n8 = ROWS * HQ / 8;
        convert_u<<<(n8 + 255) / 256, 256>>>((const float4*)u, (__half2*)uh, n8);
    }

    // GEMM1: Yh[32768,768] = uh @ Wh^T  (fp16 out)
    {
        dim3 grid(3 * PQ / BN, ROWS / BM);
        gemm_h<false><<<grid, 256, GSMEM>>>(uh, Wh, Yh, ROWS, 3 * PQ, HQ, nullptr, nullptr);
    }

    // Scan: paired channels, LC=32; warp-parallel cross-chunk scan
    {
        int nthreads = BQ * (PQ / 2) * NCHUNK;   // 131072
        scan_passA<<<nthreads / 256, 256>>>(A_diag);
        scan_passB<<<(BQ * PQ * 32) / 256, 256>>>();
        scan_passC<<<nthreads / 256, 256>>>(A_diag);
    }

    // GEMM2: out = Xh @ Ch^T + D .* u  (fp32 out, u via fp16 copy)
    {
        dim3 grid(HQ / BN, ROWS / BM);
        gemm_h<true><<<grid, 256, GSMEM>>>(Xh, Ch, out, ROWS, HQ, 2 * PQ, D, uh);
    }
}